// round 1
// baseline (speedup 1.0000x reference)
#include <cuda_runtime.h>
#include <cstdint>

#define T_TOK 4096
#define HID   2048
#define QD    2048
#define INTER_N 10944

// Scratch (allocation-free rule: __device__ globals)
__device__ float g_hnorm[(size_t)T_TOK * HID];
__device__ float g_q[(size_t)T_TOK * QD];
__device__ float g_hidden[(size_t)T_TOK * HID];
__device__ float g_hpost[(size_t)T_TOK * HID];
__device__ float g_prod[(size_t)T_TOK * INTER_N];

// ---------------- RMSNorm: one block per row, H=2048 ----------------
__global__ void rmsnorm_kernel(const float* __restrict__ x,
                               const float* __restrict__ w,
                               float* __restrict__ out) {
    const int row = blockIdx.x;
    const float4* xr = (const float4*)(x + (size_t)row * HID);
    float4* orow = (float4*)(out + (size_t)row * HID);
    const float4* wv4 = (const float4*)w;

    float4 v[2];
    float ss = 0.f;
#pragma unroll
    for (int i = 0; i < 2; i++) {
        v[i] = xr[threadIdx.x + i * 256];
        ss += v[i].x * v[i].x + v[i].y * v[i].y + v[i].z * v[i].z + v[i].w * v[i].w;
    }
#pragma unroll
    for (int o = 16; o; o >>= 1) ss += __shfl_xor_sync(0xffffffffu, ss, o);

    __shared__ float sred[8];
    if ((threadIdx.x & 31) == 0) sred[threadIdx.x >> 5] = ss;
    __syncthreads();
    if (threadIdx.x < 8) {
        float t = sred[threadIdx.x];
#pragma unroll
        for (int o = 4; o; o >>= 1) t += __shfl_xor_sync(0xffu, t, o);
        if (threadIdx.x == 0) sred[0] = t;
    }
    __syncthreads();
    const float scale = rsqrtf(sred[0] * (1.0f / HID) + 1e-6f);

#pragma unroll
    for (int i = 0; i < 2; i++) {
        float4 wv = wv4[threadIdx.x + i * 256];
        float4 o4;
        o4.x = v[i].x * scale * wv.x;
        o4.y = v[i].y * scale * wv.y;
        o4.z = v[i].z * scale * wv.z;
        o4.w = v[i].w * scale * wv.w;
        orow[threadIdx.x + i * 256] = o4;
    }
}

// ---------------- GEMM: C[m,n] = epi( sum_k A[m,k]*B[n,k] ) ----------------
// A: [M, K] row-major (M = 4096 always, divisible by 128)
// B: [N, K] row-major (weights are [out, in]); N may not be divisible by 128
// EPI: 0 = store, 1 = silu store, 2 = multiply into existing C, 3 = add Res
template <int EPI>
__global__ void __launch_bounds__(256, 2)
gemm_tn(const float* __restrict__ A, const float* __restrict__ B,
        float* __restrict__ C, const float* __restrict__ Res,
        int N, int K) {
    __shared__ float As[16][128];
    __shared__ float Bs[16][128];

    const int bm = blockIdx.y * 128;
    const int bn = blockIdx.x * 128;
    const int tid = (int)threadIdx.x;
    const int tm = (tid >> 4) << 3;   // 0..120
    const int tn = (tid & 15) << 3;   // 0..120

    // loader mapping: each thread loads rows r0 and r0+64, 4 consecutive k at c0
    const int r0 = tid >> 2;          // 0..63
    const int c0 = (tid & 3) << 2;    // 0,4,8,12

    const float* Aptr0 = A + (size_t)(bm + r0) * K + c0;
    const float* Aptr1 = A + (size_t)(bm + r0 + 64) * K + c0;
    // Clamp out-of-range B rows; their accumulators are never stored.
    int gn0 = bn + r0;       if (gn0 > N - 1) gn0 = N - 1;
    int gn1 = bn + r0 + 64;  if (gn1 > N - 1) gn1 = N - 1;
    const float* Bptr0 = B + (size_t)gn0 * K + c0;
    const float* Bptr1 = B + (size_t)gn1 * K + c0;

    float acc[8][8];
#pragma unroll
    for (int i = 0; i < 8; i++)
#pragma unroll
        for (int j = 0; j < 8; j++) acc[i][j] = 0.f;

    float4 a0 = *(const float4*)(Aptr0);
    float4 a1 = *(const float4*)(Aptr1);
    float4 b0 = *(const float4*)(Bptr0);
    float4 b1 = *(const float4*)(Bptr1);

    int k0 = 0;
    while (true) {
        As[c0 + 0][r0] = a0.x; As[c0 + 1][r0] = a0.y;
        As[c0 + 2][r0] = a0.z; As[c0 + 3][r0] = a0.w;
        As[c0 + 0][r0 + 64] = a1.x; As[c0 + 1][r0 + 64] = a1.y;
        As[c0 + 2][r0 + 64] = a1.z; As[c0 + 3][r0 + 64] = a1.w;
        Bs[c0 + 0][r0] = b0.x; Bs[c0 + 1][r0] = b0.y;
        Bs[c0 + 2][r0] = b0.z; Bs[c0 + 3][r0] = b0.w;
        Bs[c0 + 0][r0 + 64] = b1.x; Bs[c0 + 1][r0 + 64] = b1.y;
        Bs[c0 + 2][r0 + 64] = b1.z; Bs[c0 + 3][r0 + 64] = b1.w;
        __syncthreads();

        const int k1 = k0 + 16;
        if (k1 < K) {  // prefetch next k-tile while computing
            a0 = *(const float4*)(Aptr0 + k1);
            a1 = *(const float4*)(Aptr1 + k1);
            b0 = *(const float4*)(Bptr0 + k1);
            b1 = *(const float4*)(Bptr1 + k1);
        }

#pragma unroll
        for (int k = 0; k < 16; k++) {
            float4 aA = *(const float4*)&As[k][tm];
            float4 aB = *(const float4*)&As[k][tm + 4];
            float4 bA = *(const float4*)&Bs[k][tn];
            float4 bB = *(const float4*)&Bs[k][tn + 4];
            float a[8] = {aA.x, aA.y, aA.z, aA.w, aB.x, aB.y, aB.z, aB.w};
            float b[8] = {bA.x, bA.y, bA.z, bA.w, bB.x, bB.y, bB.z, bB.w};
#pragma unroll
            for (int i = 0; i < 8; i++)
#pragma unroll
                for (int j = 0; j < 8; j++)
                    acc[i][j] = fmaf(a[i], b[j], acc[i][j]);
        }
        __syncthreads();

        k0 = k1;
        if (k0 >= K) break;
    }

    // epilogue
#pragma unroll
    for (int i = 0; i < 8; i++) {
        const int gm = bm + tm + i;
        float* crow = C + (size_t)gm * N;
        const float* rrow = (EPI == 3) ? (Res + (size_t)gm * N) : nullptr;
#pragma unroll
        for (int j = 0; j < 8; j++) {
            const int gn = bn + tn + j;
            if (gn < N) {
                float v = acc[i][j];
                if (EPI == 1) v = v / (1.f + __expf(-v));     // silu
                else if (EPI == 2) v = v * crow[gn];          // up * silu(gate)
                else if (EPI == 3) v = v + rrow[gn];          // + residual
                crow[gn] = v;
            }
        }
    }
}

extern "C" void kernel_launch(void* const* d_in, const int* in_sizes, int n_in,
                              void* d_out, int out_size) {
    const float* x      = (const float*)d_in[0];
    // d_in[1] = positions (int32) — unused by the reference math
    const float* in_w   = (const float*)d_in[2];
    const float* post_w = (const float*)d_in[3];
    const float* Wq     = (const float*)d_in[4];
    const float* Wo     = (const float*)d_in[5];
    const float* Wg     = (const float*)d_in[6];
    const float* Wu     = (const float*)d_in[7];
    const float* Wd     = (const float*)d_in[8];
    float* out = (float*)d_out;

    float *hnorm, *q, *hidden, *hpost, *prod;
    cudaGetSymbolAddress((void**)&hnorm,  g_hnorm);
    cudaGetSymbolAddress((void**)&q,      g_q);
    cudaGetSymbolAddress((void**)&hidden, g_hidden);
    cudaGetSymbolAddress((void**)&hpost,  g_hpost);
    cudaGetSymbolAddress((void**)&prod,   g_prod);

    const int MT = T_TOK / 128;  // 32

    // 1. input_layernorm
    rmsnorm_kernel<<<T_TOK, 256>>>(x, in_w, hnorm);
    // 2. q = hnorm @ Wq^T
    gemm_tn<0><<<dim3(QD / 128, MT), 256>>>(hnorm, Wq, q, nullptr, QD, HID);
    // 3. hidden = x + q @ Wo^T
    gemm_tn<3><<<dim3(HID / 128, MT), 256>>>(q, Wo, hidden, x, HID, QD);
    // 4. post_attention_layernorm
    rmsnorm_kernel<<<T_TOK, 256>>>(hidden, post_w, hpost);
    // 5. prod = silu(hpost @ Wg^T)
    gemm_tn<1><<<dim3((INTER_N + 127) / 128, MT), 256>>>(hpost, Wg, prod, nullptr, INTER_N, HID);
    // 6. prod *= hpost @ Wu^T
    gemm_tn<2><<<dim3((INTER_N + 127) / 128, MT), 256>>>(hpost, Wu, prod, nullptr, INTER_N, HID);
    // 7. out = hidden + prod @ Wd^T
    gemm_tn<3><<<dim3(HID / 128, MT), 256>>>(prod, Wd, out, hidden, HID, INTER_N);
}

// round 5
// speedup vs baseline: 3.2416x; 3.2416x over previous
#include <cuda_runtime.h>
#include <cuda_bf16.h>
#include <cstdint>

#define T_TOK 4096
#define HID   2048
#define QD    2048
#define INTER_N 10944

// ---------------- scratch (__device__ globals; no allocs allowed) ----------------
// Split-bf16 layouts: [rows][2*K]  (hi at col k, lo at col K+k)
__device__ __nv_bfloat16 g_w2q[(size_t)QD * 2 * HID];
__device__ __nv_bfloat16 g_w2o[(size_t)HID * 2 * QD];
__device__ __nv_bfloat16 g_w2g[(size_t)INTER_N * 2 * HID];
__device__ __nv_bfloat16 g_w2u[(size_t)INTER_N * 2 * HID];
__device__ __nv_bfloat16 g_w2d[(size_t)HID * 2 * INTER_N];
__device__ __nv_bfloat16 g_a2h[(size_t)T_TOK * 2 * HID];     // rmsnorm(x) split
__device__ __nv_bfloat16 g_a2q[(size_t)T_TOK * 2 * QD];      // q split
__device__ __nv_bfloat16 g_a2p[(size_t)T_TOK * 2 * HID];     // rmsnorm(hidden) split
__device__ __nv_bfloat16 g_a2m[(size_t)T_TOK * 2 * INTER_N]; // silu(gate)*up split
__device__ float g_hidden[(size_t)T_TOK * HID];
__device__ float g_prodf[(size_t)T_TOK * INTER_N];           // silu(gate) fp32

// ---------------- PTX helpers (all non-arch-specific: sm_80/sm_90 base ISA) ----------------
__device__ __forceinline__ uint32_t smem_u32(const void* p) {
    uint32_t a;
    asm("{ .reg .u64 t; cvta.to.shared.u64 t, %1; cvt.u32.u64 %0, t; }" : "=r"(a) : "l"(p));
    return a;
}
#define CP16(dst, src)   asm volatile("cp.async.cg.shared.global [%0], [%1], 16;" :: "r"(dst), "l"(src) : "memory")
#define CP_COMMIT()      asm volatile("cp.async.commit_group;" ::: "memory")
#define CP_WAIT1()       asm volatile("cp.async.wait_group 1;" ::: "memory")

__device__ __forceinline__ void ldm_x4(uint32_t* r, uint32_t addr) {
    asm volatile("ldmatrix.sync.aligned.m8n8.x4.shared.b16 {%0,%1,%2,%3}, [%4];"
                 : "=r"(r[0]), "=r"(r[1]), "=r"(r[2]), "=r"(r[3]) : "r"(addr));
}
__device__ __forceinline__ void mma_bf16(float* c, const uint32_t* a, const uint32_t* b) {
    asm volatile(
        "mma.sync.aligned.m16n8k16.row.col.f32.bf16.bf16.f32 "
        "{%0,%1,%2,%3}, {%4,%5,%6,%7}, {%8,%9}, {%0,%1,%2,%3};"
        : "+f"(c[0]), "+f"(c[1]), "+f"(c[2]), "+f"(c[3])
        : "r"(a[0]), "r"(a[1]), "r"(a[2]), "r"(a[3]), "r"(b[0]), "r"(b[1]));
}

__device__ __forceinline__ void split2(float v, __nv_bfloat16& h, __nv_bfloat16& l) {
    h = __float2bfloat16(v);
    l = __float2bfloat16(v - __bfloat162float(h));
}

// ---------------- weight split: W[N,K] fp32 -> [N][2K] bf16 (hi|lo) ----------------
__global__ void split_w_kernel(const float* __restrict__ W, __nv_bfloat16* __restrict__ O,
                               unsigned K, unsigned total4) {
    unsigned i = blockIdx.x * blockDim.x + threadIdx.x;
    const unsigned stride = gridDim.x * blockDim.x;
    for (; i < total4; i += stride) {
        unsigned e = i * 4u;
        unsigned row = e / K;
        unsigned col = e - row * K;
        float4 v = reinterpret_cast<const float4*>(W)[i];
        size_t b = (size_t)row * (2 * (size_t)K) + col;
        __nv_bfloat16 h0, l0, h1, l1, h2, l2, h3, l3;
        split2(v.x, h0, l0); split2(v.y, h1, l1); split2(v.z, h2, l2); split2(v.w, h3, l3);
        O[b] = h0; O[b + 1] = h1; O[b + 2] = h2; O[b + 3] = h3;
        O[b + K] = l0; O[b + K + 1] = l1; O[b + K + 2] = l2; O[b + K + 3] = l3;
    }
}

// ---------------- RMSNorm -> split bf16 [row][2*HID] ----------------
__global__ void rmsnorm_split_kernel(const float* __restrict__ x,
                                     const float* __restrict__ w,
                                     __nv_bfloat16* __restrict__ out) {
    const int row = blockIdx.x;
    const float4* xr = (const float4*)(x + (size_t)row * HID);
    const float4* wv4 = (const float4*)w;

    float4 v[2];
    float ss = 0.f;
#pragma unroll
    for (int i = 0; i < 2; i++) {
        v[i] = xr[threadIdx.x + i * 256];
        ss += v[i].x * v[i].x + v[i].y * v[i].y + v[i].z * v[i].z + v[i].w * v[i].w;
    }
#pragma unroll
    for (int o = 16; o; o >>= 1) ss += __shfl_xor_sync(0xffffffffu, ss, o);
    __shared__ float sred[8];
    if ((threadIdx.x & 31) == 0) sred[threadIdx.x >> 5] = ss;
    __syncthreads();
    if (threadIdx.x < 8) {
        float t = sred[threadIdx.x];
#pragma unroll
        for (int o = 4; o; o >>= 1) t += __shfl_xor_sync(0xffu, t, o);
        if (threadIdx.x == 0) sred[0] = t;
    }
    __syncthreads();
    const float scale = rsqrtf(sred[0] * (1.0f / HID) + 1e-6f);

    __nv_bfloat16* orow = out + (size_t)row * 2 * HID;
#pragma unroll
    for (int i = 0; i < 2; i++) {
        float4 wv = wv4[threadIdx.x + i * 256];
        int c = (threadIdx.x + i * 256) * 4;
        float f[4] = { v[i].x * scale * wv.x, v[i].y * scale * wv.y,
                       v[i].z * scale * wv.z, v[i].w * scale * wv.w };
#pragma unroll
        for (int j = 0; j < 4; j++) {
            __nv_bfloat16 h, l;
            split2(f[j], h, l);
            orow[c + j] = h;
            orow[HID + c + j] = l;
        }
    }
}

// ---------------- HMMA GEMM: C[m,n] = epi(sum_k A[m,k]*B[n,k]) over K'=3K ----------------
// A: [4096][2K] bf16 (hi|lo), B: [N][2K] bf16 (hi|lo). CTA tile 128x128, BK=64.
// 3-stage cp.async pipeline, SW128 swizzle, ldmatrix + mma.sync.m16n8k16.
// EPI: 1 = silu->C ; 2 = acc*C -> split Dst ; 3 = acc+Res -> C ; 4 = split Dst
#define NSTAGE 3
#define STG    32768           // 16KB A + 16KB B per stage
#define SMEM_TOTAL (NSTAGE * STG)

template <int EPI>
__global__ void __launch_bounds__(256, 2)
gemm_bf16s(const __nv_bfloat16* __restrict__ A, const __nv_bfloat16* __restrict__ B,
           float* __restrict__ C, const float* __restrict__ Res,
           __nv_bfloat16* __restrict__ Dst, int N, int K) {
    extern __shared__ __align__(1024) char smem[];
    const uint32_t sb = smem_u32(smem);
    const int tid = threadIdx.x;
    const int lane = tid & 31;
    const int w = tid >> 5;
    const int mw = w >> 2;            // 0..1  (64-row slab)
    const int nw = w & 3;             // 0..3  (32-col slab)
    const int bm = blockIdx.y * 128;
    const int bn = blockIdx.x * 128;
    const int Kc = K >> 6;            // 64-elem chunks per region
    const int nch = 3 * Kc;
    const uint32_t strideAB = 2u * (uint32_t)K;   // elements per row

    // ---- loader precompute: 4 x 16B chunks each for A and B per thread ----
    const char* Abase = (const char*)A;
    const char* Bbase = (const char*)B;
    uint32_t la_dst[4], lb_dst[4], la_off[4], lb_off[4];
#pragma unroll
    for (int i = 0; i < 4; i++) {
        int idx = tid + 256 * i, r = idx >> 3, c = idx & 7;
        uint32_t sw = (uint32_t)(r * 128 + ((c * 16) ^ ((r & 7) << 4)));
        la_dst[i] = sw;
        la_off[i] = ((uint32_t)(bm + r) * strideAB + (uint32_t)c * 8u) * 2u;
        int gr = bn + r; if (gr > N - 1) gr = N - 1;
        lb_dst[i] = sw;
        lb_off[i] = ((uint32_t)gr * strideAB + (uint32_t)c * 8u) * 2u;
    }

    auto load_stage = [&](int stage, int ch) {
        int ca = (ch < 2 * Kc) ? ch : ch - 2 * Kc;   // A: [Ah|Al|Ah]
        int cb = (ch < Kc) ? ch : ch - Kc;           // B: [Bh|Bh|Bl]
        uint32_t ab = sb + stage * STG;
        uint32_t bb = ab + 16384;
        uint32_t cao = (uint32_t)ca * 128u;          // 64 elems * 2B
        uint32_t cbo = (uint32_t)cb * 128u;
#pragma unroll
        for (int i = 0; i < 4; i++) CP16(ab + la_dst[i], Abase + la_off[i] + cao);
#pragma unroll
        for (int i = 0; i < 4; i++) CP16(bb + lb_dst[i], Bbase + lb_off[i] + cbo);
        CP_COMMIT();
    };

    // ---- ldmatrix lane addressing (within a stage buffer) ----
    // A: lanes 0-15 -> rows m0+l @k0, lanes 16-31 -> rows @k8
    const int arow = mw * 64 + (lane & 15);
    const uint32_t a_xor = (uint32_t)((arow & 7) << 4);
    const uint32_t a_rb = (uint32_t)(arow * 128);
    const uint32_t a_k0 = (uint32_t)((lane >> 4) * 16);
    // B: lanes 0-7 rows n0..7 @k0 ; 8-15 same rows @k8 ; 16-23 rows+8 @k0 ; 24-31 rows+8 @k8
    const int brow = nw * 32 + ((lane >> 4) & 1) * 8 + (lane & 7);
    const uint32_t b_xor = (uint32_t)((brow & 7) << 4);
    const uint32_t b_rb = (uint32_t)(brow * 128);
    const uint32_t b_k0 = (uint32_t)(((lane >> 3) & 1) * 16);

    float acc[4][4][4];
#pragma unroll
    for (int i = 0; i < 4; i++)
#pragma unroll
        for (int j = 0; j < 4; j++)
#pragma unroll
            for (int q = 0; q < 4; q++) acc[i][j][q] = 0.f;

    // ---- pipeline ----
    load_stage(0, 0);
    load_stage(1, 1);

    for (int s = 0; s < nch; s++) {
        const int stage = s % NSTAGE;
        CP_WAIT1();
        __syncthreads();

        const uint32_t sA = sb + stage * STG;
        const uint32_t sB = sA + 16384;
#pragma unroll
        for (int kk = 0; kk < 4; kk++) {
            uint32_t af[4][4], bf[2][4];
#pragma unroll
            for (int ma = 0; ma < 4; ma++)
                ldm_x4(af[ma], sA + a_rb + (uint32_t)(ma * 2048) + ((kk * 32 + a_k0) ^ a_xor));
#pragma unroll
            for (int nb = 0; nb < 2; nb++)
                ldm_x4(bf[nb], sB + b_rb + (uint32_t)(nb * 2048) + ((kk * 32 + b_k0) ^ b_xor));
#pragma unroll
            for (int ma = 0; ma < 4; ma++)
#pragma unroll
                for (int na = 0; na < 4; na++)
                    mma_bf16(acc[ma][na], af[ma], &bf[na >> 1][(na & 1) * 2]);
        }

        const int nc = s + 2;
        if (nc < nch) load_stage(nc % NSTAGE, nc);
        else          CP_COMMIT();   // empty group keeps wait_group accounting exact
    }

    // ---- epilogue ----
#pragma unroll
    for (int ma = 0; ma < 4; ma++) {
        const int gm0 = bm + mw * 64 + ma * 16 + (lane >> 2);
#pragma unroll
        for (int na = 0; na < 4; na++) {
            const int gn = bn + nw * 32 + na * 8 + (lane & 3) * 2;
            if (gn >= N) continue;
            const float* c = acc[ma][na];
#pragma unroll
            for (int h = 0; h < 2; h++) {
                const int gm = gm0 + h * 8;
                float v0 = c[h * 2 + 0], v1 = c[h * 2 + 1];
                if (EPI == 1) {
                    float2 o;
                    o.x = v0 / (1.f + __expf(-v0));
                    o.y = v1 / (1.f + __expf(-v1));
                    *(float2*)(C + (size_t)gm * N + gn) = o;
                } else if (EPI == 2) {
                    float2 g = *(const float2*)(C + (size_t)gm * N + gn);
                    v0 *= g.x; v1 *= g.y;
                    __nv_bfloat16 h0, l0, h1, l1;
                    split2(v0, h0, l0); split2(v1, h1, l1);
                    *(__nv_bfloat162*)(Dst + (size_t)gm * 2 * N + gn) = __nv_bfloat162(h0, h1);
                    *(__nv_bfloat162*)(Dst + (size_t)gm * 2 * N + N + gn) = __nv_bfloat162(l0, l1);
                } else if (EPI == 3) {
                    float2 rr = *(const float2*)(Res + (size_t)gm * N + gn);
                    float2 o; o.x = v0 + rr.x; o.y = v1 + rr.y;
                    *(float2*)(C + (size_t)gm * N + gn) = o;
                } else {  // EPI == 4
                    __nv_bfloat16 h0, l0, h1, l1;
                    split2(v0, h0, l0); split2(v1, h1, l1);
                    *(__nv_bfloat162*)(Dst + (size_t)gm * 2 * N + gn) = __nv_bfloat162(h0, h1);
                    *(__nv_bfloat162*)(Dst + (size_t)gm * 2 * N + N + gn) = __nv_bfloat162(l0, l1);
                }
            }
        }
    }
}

// ---------------- launch ----------------
extern "C" void kernel_launch(void* const* d_in, const int* in_sizes, int n_in,
                              void* d_out, int out_size) {
    const float* x      = (const float*)d_in[0];
    const float* in_w   = (const float*)d_in[2];
    const float* post_w = (const float*)d_in[3];
    const float* Wq     = (const float*)d_in[4];
    const float* Wo     = (const float*)d_in[5];
    const float* Wg     = (const float*)d_in[6];
    const float* Wu     = (const float*)d_in[7];
    const float* Wd     = (const float*)d_in[8];
    float* out = (float*)d_out;

    __nv_bfloat16 *w2q, *w2o, *w2g, *w2u, *w2d, *a2h, *a2q, *a2p, *a2m;
    float *hidden, *prodf;
    cudaGetSymbolAddress((void**)&w2q, g_w2q);
    cudaGetSymbolAddress((void**)&w2o, g_w2o);
    cudaGetSymbolAddress((void**)&w2g, g_w2g);
    cudaGetSymbolAddress((void**)&w2u, g_w2u);
    cudaGetSymbolAddress((void**)&w2d, g_w2d);
    cudaGetSymbolAddress((void**)&a2h, g_a2h);
    cudaGetSymbolAddress((void**)&a2q, g_a2q);
    cudaGetSymbolAddress((void**)&a2p, g_a2p);
    cudaGetSymbolAddress((void**)&a2m, g_a2m);
    cudaGetSymbolAddress((void**)&hidden, g_hidden);
    cudaGetSymbolAddress((void**)&prodf, g_prodf);

    cudaFuncSetAttribute(gemm_bf16s<1>, cudaFuncAttributeMaxDynamicSharedMemorySize, SMEM_TOTAL);
    cudaFuncSetAttribute(gemm_bf16s<2>, cudaFuncAttributeMaxDynamicSharedMemorySize, SMEM_TOTAL);
    cudaFuncSetAttribute(gemm_bf16s<3>, cudaFuncAttributeMaxDynamicSharedMemorySize, SMEM_TOTAL);
    cudaFuncSetAttribute(gemm_bf16s<4>, cudaFuncAttributeMaxDynamicSharedMemorySize, SMEM_TOTAL);

    // weight splits
    split_w_kernel<<<2048, 256>>>(Wq, w2q, HID, (unsigned)((size_t)QD * HID / 4));
    split_w_kernel<<<2048, 256>>>(Wo, w2o, QD, (unsigned)((size_t)HID * QD / 4));
    split_w_kernel<<<2048, 256>>>(Wg, w2g, HID, (unsigned)((size_t)INTER_N * HID / 4));
    split_w_kernel<<<2048, 256>>>(Wu, w2u, HID, (unsigned)((size_t)INTER_N * HID / 4));
    split_w_kernel<<<2048, 256>>>(Wd, w2d, INTER_N, (unsigned)((size_t)HID * INTER_N / 4));

    const int MT = T_TOK / 128;  // 32

    // 1. input_layernorm -> split
    rmsnorm_split_kernel<<<T_TOK, 256>>>(x, in_w, a2h);
    // 2. q = hnorm @ Wq^T -> split
    gemm_bf16s<4><<<dim3(QD / 128, MT), 256, SMEM_TOTAL>>>(a2h, w2q, nullptr, nullptr, a2q, QD, HID);
    // 3. hidden = x + q @ Wo^T
    gemm_bf16s<3><<<dim3(HID / 128, MT), 256, SMEM_TOTAL>>>(a2q, w2o, hidden, x, nullptr, HID, QD);
    // 4. post_attention_layernorm -> split
    rmsnorm_split_kernel<<<T_TOK, 256>>>(hidden, post_w, a2p);
    // 5. prodf = silu(hpost @ Wg^T)
    gemm_bf16s<1><<<dim3((INTER_N + 127) / 128, MT), 256, SMEM_TOTAL>>>(a2p, w2g, prodf, nullptr, nullptr, INTER_N, HID);
    // 6. a2m = split(prodf * (hpost @ Wu^T))
    gemm_bf16s<2><<<dim3((INTER_N + 127) / 128, MT), 256, SMEM_TOTAL>>>(a2p, w2u, prodf, nullptr, a2m, INTER_N, HID);
    // 7. out = hidden + a2m @ Wd^T
    gemm_bf16s<3><<<dim3(HID / 128, MT), 256, SMEM_TOTAL>>>(a2m, w2d, out, hidden, nullptr, HID, INTER_N);
}

// round 7
// speedup vs baseline: 8.7658x; 2.7042x over previous
#include <cuda_runtime.h>
#include <cuda_fp16.h>
#include <cstdint>

#define T_TOK 4096
#define HID   2048
#define QD    2048
#define INTER_N 10944

// ---------------- scratch (__device__ globals; no allocs allowed) ----------------
__device__ __half g_w16q[(size_t)QD * HID];
__device__ __half g_w16o[(size_t)HID * QD];
__device__ __half g_w16g[(size_t)INTER_N * HID];
__device__ __half g_w16u[(size_t)INTER_N * HID];
__device__ __half g_w16d[(size_t)HID * INTER_N];
__device__ __half g_a16h[(size_t)T_TOK * HID];     // rmsnorm(x) fp16
__device__ __half g_a16q[(size_t)T_TOK * QD];      // q fp16
__device__ __half g_a16p[(size_t)T_TOK * HID];     // rmsnorm(hidden) fp16
__device__ __half g_a16m[(size_t)T_TOK * INTER_N]; // silu(gate)*up fp16
__device__ float g_hidden[(size_t)T_TOK * HID];
__device__ float g_prodf[(size_t)T_TOK * INTER_N]; // silu(gate) fp32

// ---------------- PTX helpers ----------------
__device__ __forceinline__ uint32_t smem_u32(const void* p) {
    uint32_t a;
    asm("{ .reg .u64 t; cvta.to.shared.u64 t, %1; cvt.u32.u64 %0, t; }" : "=r"(a) : "l"(p));
    return a;
}
#define CP16(dst, src)   asm volatile("cp.async.cg.shared.global [%0], [%1], 16;" :: "r"(dst), "l"(src) : "memory")
#define CP_COMMIT()      asm volatile("cp.async.commit_group;" ::: "memory")
#define CP_WAIT1()       asm volatile("cp.async.wait_group 1;" ::: "memory")

__device__ __forceinline__ void ldm_x4(uint32_t* r, uint32_t addr) {
    asm volatile("ldmatrix.sync.aligned.m8n8.x4.shared.b16 {%0,%1,%2,%3}, [%4];"
                 : "=r"(r[0]), "=r"(r[1]), "=r"(r[2]), "=r"(r[3]) : "r"(addr));
}
__device__ __forceinline__ void mma_fp16(float* c, const uint32_t* a, const uint32_t* b) {
    asm volatile(
        "mma.sync.aligned.m16n8k16.row.col.f32.f16.f16.f32 "
        "{%0,%1,%2,%3}, {%4,%5,%6,%7}, {%8,%9}, {%0,%1,%2,%3};"
        : "+f"(c[0]), "+f"(c[1]), "+f"(c[2]), "+f"(c[3])
        : "r"(a[0]), "r"(a[1]), "r"(a[2]), "r"(a[3]), "r"(b[0]), "r"(b[1]));
}

// ---------------- weight convert: fp32 -> fp16 ----------------
__global__ void cvt_w_kernel(const float4* __restrict__ W, uint2* __restrict__ O,
                             unsigned total4) {
    unsigned i = blockIdx.x * blockDim.x + threadIdx.x;
    const unsigned stride = gridDim.x * blockDim.x;
    for (; i < total4; i += stride) {
        float4 v = W[i];
        __half2 h01 = __floats2half2_rn(v.x, v.y);
        __half2 h23 = __floats2half2_rn(v.z, v.w);
        uint2 o;
        o.x = *(uint32_t*)&h01;
        o.y = *(uint32_t*)&h23;
        O[i] = o;
    }
}

// ---------------- RMSNorm -> fp16 ----------------
__global__ void rmsnorm_f16_kernel(const float* __restrict__ x,
                                   const float* __restrict__ w,
                                   __half* __restrict__ out) {
    const int row = blockIdx.x;
    const float4* xr = (const float4*)(x + (size_t)row * HID);
    const float4* wv4 = (const float4*)w;

    float4 v[2];
    float ss = 0.f;
#pragma unroll
    for (int i = 0; i < 2; i++) {
        v[i] = xr[threadIdx.x + i * 256];
        ss += v[i].x * v[i].x + v[i].y * v[i].y + v[i].z * v[i].z + v[i].w * v[i].w;
    }
#pragma unroll
    for (int o = 16; o; o >>= 1) ss += __shfl_xor_sync(0xffffffffu, ss, o);
    __shared__ float sred[8];
    if ((threadIdx.x & 31) == 0) sred[threadIdx.x >> 5] = ss;
    __syncthreads();
    if (threadIdx.x < 8) {
        float t = sred[threadIdx.x];
#pragma unroll
        for (int o = 4; o; o >>= 1) t += __shfl_xor_sync(0xffu, t, o);
        if (threadIdx.x == 0) sred[0] = t;
    }
    __syncthreads();
    const float scale = rsqrtf(sred[0] * (1.0f / HID) + 1e-6f);

    uint2* orow = (uint2*)(out + (size_t)row * HID);
#pragma unroll
    for (int i = 0; i < 2; i++) {
        float4 wv = wv4[threadIdx.x + i * 256];
        __half2 h01 = __floats2half2_rn(v[i].x * scale * wv.x, v[i].y * scale * wv.y);
        __half2 h23 = __floats2half2_rn(v[i].z * scale * wv.z, v[i].w * scale * wv.w);
        uint2 o;
        o.x = *(uint32_t*)&h01;
        o.y = *(uint32_t*)&h23;
        orow[threadIdx.x + i * 256] = o;
    }
}

// ---------------- HMMA GEMM: C[m,n] = epi(sum_k A[m,k]*B[n,k]), fp16 single-pass ----------------
// A: [4096][K] fp16, B: [N][K] fp16. CTA tile 128x128, BK=64.
// 3-stage cp.async pipeline, SW128 swizzle, ldmatrix + mma.sync.m16n8k16.
// EPI: 1 = silu->C(f32) ; 2 = acc*C -> Dst(f16) ; 3 = acc+Res -> C(f32) ; 4 = Dst(f16)
#define NSTAGE 3
#define STG    32768           // 16KB A + 16KB B per stage
#define SMEM_TOTAL (NSTAGE * STG)

template <int EPI>
__global__ void __launch_bounds__(256, 2)
gemm_f16(const __half* __restrict__ A, const __half* __restrict__ B,
         float* __restrict__ C, const float* __restrict__ Res,
         __half* __restrict__ Dst, int N, int K) {
    extern __shared__ __align__(1024) char smem[];
    const uint32_t sb = smem_u32(smem);
    const int tid = threadIdx.x;
    const int lane = tid & 31;
    const int w = tid >> 5;
    const int mw = w >> 2;            // 0..1  (64-row slab)
    const int nw = w & 3;             // 0..3  (32-col slab)
    const int bm = blockIdx.y * 128;
    const int bn = blockIdx.x * 128;
    const int nch = K >> 6;           // 64-elem chunks
    const uint32_t strideK = (uint32_t)K;

    // ---- loader precompute: 4 x 16B chunks each for A and B per thread ----
    const char* Abase = (const char*)A;
    const char* Bbase = (const char*)B;
    uint32_t l_dst[4], la_off[4], lb_off[4];
#pragma unroll
    for (int i = 0; i < 4; i++) {
        int idx = tid + 256 * i, r = idx >> 3, c = idx & 7;
        l_dst[i] = (uint32_t)(r * 128 + ((c * 16) ^ ((r & 7) << 4)));
        la_off[i] = ((uint32_t)(bm + r) * strideK + (uint32_t)c * 8u) * 2u;
        int gr = bn + r; if (gr > N - 1) gr = N - 1;
        lb_off[i] = ((uint32_t)gr * strideK + (uint32_t)c * 8u) * 2u;
    }

    auto load_stage = [&](int stage, int ch) {
        uint32_t ab = sb + stage * STG;
        uint32_t bb = ab + 16384;
        uint32_t co = (uint32_t)ch * 128u;           // 64 halfs = 128 bytes
#pragma unroll
        for (int i = 0; i < 4; i++) CP16(ab + l_dst[i], Abase + la_off[i] + co);
#pragma unroll
        for (int i = 0; i < 4; i++) CP16(bb + l_dst[i], Bbase + lb_off[i] + co);
        CP_COMMIT();
    };

    // ---- ldmatrix lane addressing ----
    const int arow = mw * 64 + (lane & 15);
    const uint32_t a_xor = (uint32_t)((arow & 7) << 4);
    const uint32_t a_rb = (uint32_t)(arow * 128);
    const uint32_t a_k0 = (uint32_t)((lane >> 4) * 16);
    const int brow = nw * 32 + ((lane >> 4) & 1) * 8 + (lane & 7);
    const uint32_t b_xor = (uint32_t)((brow & 7) << 4);
    const uint32_t b_rb = (uint32_t)(brow * 128);
    const uint32_t b_k0 = (uint32_t)(((lane >> 3) & 1) * 16);

    float acc[4][4][4];
#pragma unroll
    for (int i = 0; i < 4; i++)
#pragma unroll
        for (int j = 0; j < 4; j++)
#pragma unroll
            for (int q = 0; q < 4; q++) acc[i][j][q] = 0.f;

    // ---- pipeline ----
    load_stage(0, 0);
    load_stage(1, 1);

    for (int s = 0; s < nch; s++) {
        const int stage = s % NSTAGE;
        CP_WAIT1();
        __syncthreads();

        const uint32_t sA = sb + stage * STG;
        const uint32_t sB = sA + 16384;
#pragma unroll
        for (int kk = 0; kk < 4; kk++) {
            uint32_t af[4][4], bf[2][4];
#pragma unroll
            for (int ma = 0; ma < 4; ma++)
                ldm_x4(af[ma], sA + a_rb + (uint32_t)(ma * 2048) + ((kk * 32 + a_k0) ^ a_xor));
#pragma unroll
            for (int nb = 0; nb < 2; nb++)
                ldm_x4(bf[nb], sB + b_rb + (uint32_t)(nb * 2048) + ((kk * 32 + b_k0) ^ b_xor));
#pragma unroll
            for (int ma = 0; ma < 4; ma++)
#pragma unroll
                for (int na = 0; na < 4; na++)
                    mma_fp16(acc[ma][na], af[ma], &bf[na >> 1][(na & 1) * 2]);
        }

        const int nc = s + 2;
        if (nc < nch) load_stage(nc % NSTAGE, nc);
        else          CP_COMMIT();   // empty group keeps wait_group accounting exact
    }

    // ---- epilogue ----
#pragma unroll
    for (int ma = 0; ma < 4; ma++) {
        const int gm0 = bm + mw * 64 + ma * 16 + (lane >> 2);
#pragma unroll
        for (int na = 0; na < 4; na++) {
            const int gn = bn + nw * 32 + na * 8 + (lane & 3) * 2;
            if (gn >= N) continue;
            const float* c = acc[ma][na];
#pragma unroll
            for (int h = 0; h < 2; h++) {
                const int gm = gm0 + h * 8;
                float v0 = c[h * 2 + 0], v1 = c[h * 2 + 1];
                if (EPI == 1) {
                    float2 o;
                    o.x = v0 / (1.f + __expf(-v0));
                    o.y = v1 / (1.f + __expf(-v1));
                    *(float2*)(C + (size_t)gm * N + gn) = o;
                } else if (EPI == 2) {
                    float2 g = *(const float2*)(C + (size_t)gm * N + gn);
                    __half2 o = __floats2half2_rn(v0 * g.x, v1 * g.y);
                    *(__half2*)(Dst + (size_t)gm * N + gn) = o;
                } else if (EPI == 3) {
                    float2 rr = *(const float2*)(Res + (size_t)gm * N + gn);
                    float2 o; o.x = v0 + rr.x; o.y = v1 + rr.y;
                    *(float2*)(C + (size_t)gm * N + gn) = o;
                } else {  // EPI == 4
                    __half2 o = __floats2half2_rn(v0, v1);
                    *(__half2*)(Dst + (size_t)gm * N + gn) = o;
                }
            }
        }
    }
}

// ---------------- launch ----------------
extern "C" void kernel_launch(void* const* d_in, const int* in_sizes, int n_in,
                              void* d_out, int out_size) {
    const float* x      = (const float*)d_in[0];
    const float* in_w   = (const float*)d_in[2];
    const float* post_w = (const float*)d_in[3];
    const float* Wq     = (const float*)d_in[4];
    const float* Wo     = (const float*)d_in[5];
    const float* Wg     = (const float*)d_in[6];
    const float* Wu     = (const float*)d_in[7];
    const float* Wd     = (const float*)d_in[8];
    float* out = (float*)d_out;

    __half *w16q, *w16o, *w16g, *w16u, *w16d, *a16h, *a16q, *a16p, *a16m;
    float *hidden, *prodf;
    cudaGetSymbolAddress((void**)&w16q, g_w16q);
    cudaGetSymbolAddress((void**)&w16o, g_w16o);
    cudaGetSymbolAddress((void**)&w16g, g_w16g);
    cudaGetSymbolAddress((void**)&w16u, g_w16u);
    cudaGetSymbolAddress((void**)&w16d, g_w16d);
    cudaGetSymbolAddress((void**)&a16h, g_a16h);
    cudaGetSymbolAddress((void**)&a16q, g_a16q);
    cudaGetSymbolAddress((void**)&a16p, g_a16p);
    cudaGetSymbolAddress((void**)&a16m, g_a16m);
    cudaGetSymbolAddress((void**)&hidden, g_hidden);
    cudaGetSymbolAddress((void**)&prodf, g_prodf);

    cudaFuncSetAttribute(gemm_f16<1>, cudaFuncAttributeMaxDynamicSharedMemorySize, SMEM_TOTAL);
    cudaFuncSetAttribute(gemm_f16<2>, cudaFuncAttributeMaxDynamicSharedMemorySize, SMEM_TOTAL);
    cudaFuncSetAttribute(gemm_f16<3>, cudaFuncAttributeMaxDynamicSharedMemorySize, SMEM_TOTAL);
    cudaFuncSetAttribute(gemm_f16<4>, cudaFuncAttributeMaxDynamicSharedMemorySize, SMEM_TOTAL);

    // weight converts (fp32 -> fp16)
    cvt_w_kernel<<<2048, 256>>>((const float4*)Wq, (uint2*)w16q, (unsigned)((size_t)QD * HID / 4));
    cvt_w_kernel<<<2048, 256>>>((const float4*)Wo, (uint2*)w16o, (unsigned)((size_t)HID * QD / 4));
    cvt_w_kernel<<<2048, 256>>>((const float4*)Wg, (uint2*)w16g, (unsigned)((size_t)INTER_N * HID / 4));
    cvt_w_kernel<<<2048, 256>>>((const float4*)Wu, (uint2*)w16u, (unsigned)((size_t)INTER_N * HID / 4));
    cvt_w_kernel<<<2048, 256>>>((const float4*)Wd, (uint2*)w16d, (unsigned)((size_t)HID * INTER_N / 4));

    const int MT = T_TOK / 128;  // 32

    // 1. input_layernorm -> fp16
    rmsnorm_f16_kernel<<<T_TOK, 256>>>(x, in_w, a16h);
    // 2. q = hnorm @ Wq^T -> fp16
    gemm_f16<4><<<dim3(QD / 128, MT), 256, SMEM_TOTAL>>>(a16h, w16q, nullptr, nullptr, a16q, QD, HID);
    // 3. hidden = x + q @ Wo^T
    gemm_f16<3><<<dim3(HID / 128, MT), 256, SMEM_TOTAL>>>(a16q, w16o, hidden, x, nullptr, HID, QD);
    // 4. post_attention_layernorm -> fp16
    rmsnorm_f16_kernel<<<T_TOK, 256>>>(hidden, post_w, a16p);
    // 5. prodf = silu(hpost @ Wg^T)  (fp32)
    gemm_f16<1><<<dim3((INTER_N + 127) / 128, MT), 256, SMEM_TOTAL>>>(a16p, w16g, prodf, nullptr, nullptr, INTER_N, HID);
    // 6. a16m = fp16(prodf * (hpost @ Wu^T))
    gemm_f16<2><<<dim3((INTER_N + 127) / 128, MT), 256, SMEM_TOTAL>>>(a16p, w16u, prodf, nullptr, a16m, INTER_N, HID);
    // 7. out = hidden + a16m @ Wd^T
    gemm_f16<3><<<dim3(HID / 128, MT), 256, SMEM_TOTAL>>>(a16m, w16d, out, hidden, nullptr, HID, INTER_N);
}